// round 1
// baseline (speedup 1.0000x reference)
#include <cuda_runtime.h>

#define WARPS 4
#define FULLMASK 0xffffffffu

__global__ void __launch_bounds__(128) arek(
    const float* __restrict__ q_pts, const float* __restrict__ s_pts,
    const int*   __restrict__ nbr,
    const float* __restrict__ wb,     const float* __restrict__ w_vn,
    const float* __restrict__ wd_vn,  const float* __restrict__ w_h1,
    const float* __restrict__ w_h2,   const float* __restrict__ b_h2,
    const float* __restrict__ wd_relu,const float* __restrict__ w_un,
    const float* __restrict__ wd_un,
    float* __restrict__ out, int N)
{
    __shared__ float s_wvn[48], s_wdvn[48], s_wh1[128], s_wh2[64], s_bh2[8];
    __shared__ float s_wb[768];
    __shared__ float s_wdrelu[1024];
    __shared__ float s_wun[2048], s_wdun[2048];
    __shared__ float s_local [WARPS][9][16];   // [c*3+d][k]
    __shared__ float s_scores[WARPS][8][16];   // [ks][k]
    __shared__ float s_feats [WARPS][32][3];

    const int tid = threadIdx.x;
    // ---- cooperative weight staging ----
    if (tid < 48) { s_wvn[tid] = w_vn[tid]; s_wdvn[tid] = wd_vn[tid]; }
    s_wh1[tid] = w_h1[tid];                 // 128 elements, 128 threads
    if (tid < 64) s_wh2[tid] = w_h2[tid];
    if (tid < 8)  s_bh2[tid] = b_h2[tid];
    #pragma unroll
    for (int i = tid; i < 768; i += 128) s_wb[i] = wb[i];
    #pragma unroll
    for (int i = tid; i < 1024; i += 128) s_wdrelu[i] = wd_relu[i];
    #pragma unroll
    for (int i = tid; i < 2048; i += 128) { s_wun[i] = w_un[i]; s_wdun[i] = wd_un[i]; }
    __syncthreads();

    const int warp = tid >> 5, lane = tid & 31;
    const int n = blockIdx.x * WARPS + warp;
    if (n >= N) return;

    const float BN = 0.99999500003749968f;   // 1/sqrt(1+1e-5)

    // ================= Phase 1: per-neighbor score net =================
    // lane -> (k = lane&15, kh = lane>>4); each k handled by a lane pair.
    const int k  = lane & 15;
    const int kh = lane >> 4;

    const float qx = q_pts[n*3+0], qy = q_pts[n*3+1], qz = q_pts[n*3+2];
    const int idx = nbr[n*16 + k];
    const float px = s_pts[idx*3+0] - qx;
    const float py = s_pts[idx*3+1] - qy;
    const float pz = s_pts[idx*3+2] - qz;

    // center = mean over k (each k duplicated twice across the warp -> /32)
    float cx = px, cy = py, cz = pz;
    #pragma unroll
    for (int off = 16; off; off >>= 1) {
        cx += __shfl_xor_sync(FULLMASK, cx, off);
        cy += __shfl_xor_sync(FULLMASK, cy, off);
        cz += __shfl_xor_sync(FULLMASK, cz, off);
    }
    cx *= (1.0f/32.0f); cy *= (1.0f/32.0f); cz *= (1.0f/32.0f);

    // cross(pts, center)
    const float rx = py*cz - pz*cy;
    const float ry = pz*cx - px*cz;
    const float rz = px*cy - py*cx;

    if (kh == 0) {
        s_local[warp][0][k] = px; s_local[warp][1][k] = py; s_local[warp][2][k] = pz;
        s_local[warp][3][k] = cx; s_local[warp][4][k] = cy; s_local[warp][5][k] = cz;
        s_local[warp][6][k] = rx; s_local[warp][7][k] = ry; s_local[warp][8][k] = rz;
    }

    // VN linear (3->16) + VN leaky relu + norm over d : each lane does 8 of 16 o's
    float sn[8];
    const int obase = kh * 8;
    #pragma unroll
    for (int oo = 0; oo < 8; oo++) {
        const int o = obase + oo;
        const float w0 = s_wvn[o],      w1 = s_wvn[16+o],  w2 = s_wvn[32+o];
        const float u0 = s_wdvn[o],     u1 = s_wdvn[16+o], u2 = s_wdvn[32+o];
        const float p0 = BN*(px*w0 + cx*w1 + rx*w2);
        const float p1 = BN*(py*w0 + cy*w1 + ry*w2);
        const float p2 = BN*(pz*w0 + cz*w1 + rz*w2);
        const float d0 = px*u0 + cx*u1 + rx*u2;
        const float d1 = py*u0 + cy*u1 + ry*u2;
        const float d2 = pz*u0 + cz*u1 + rz*u2;
        const float dot = p0*d0 + p1*d1 + p2*d2;
        const float dsq = d0*d0 + d1*d1 + d2*d2;
        const float f = (dot >= 0.0f) ? 0.0f : (0.8f * __fdividef(dot, dsq + 1e-6f));
        const float s0 = p0 - f*d0, s1 = p1 - f*d1, s2 = p2 - f*d2;
        sn[oo] = sqrtf(s0*s0 + s1*s1 + s2*s2);
    }

    // h1 = relu(BN * sn @ w_h1): partial over own 8 channels, combine with pair lane
    float h1[8];
    #pragma unroll
    for (int o = 0; o < 8; o++) {
        float acc = 0.0f;
        #pragma unroll
        for (int c = 0; c < 8; c++) acc += sn[c] * s_wh1[(obase + c)*8 + o];
        acc += __shfl_xor_sync(FULLMASK, acc, 16);
        h1[o] = fmaxf(0.0f, BN * acc);
    }
    // h2 + softmax over the 8 channels
    float h2[8]; float m = -1e30f;
    #pragma unroll
    for (int o = 0; o < 8; o++) {
        float acc = s_bh2[o];
        #pragma unroll
        for (int c = 0; c < 8; c++) acc += h1[c] * s_wh2[c*8 + o];
        h2[o] = acc; m = fmaxf(m, acc);
    }
    float se = 0.0f;
    #pragma unroll
    for (int o = 0; o < 8; o++) { h2[o] = __expf(h2[o] - m); se += h2[o]; }
    const float ise = __fdividef(1.0f, se);
    if (kh == 0) {
        #pragma unroll
        for (int o = 0; o < 8; o++) s_scores[warp][o][k] = h2[o] * ise;
    }
    __syncwarp();

    // ======= Phase 2: kernel-point correlation, lane = output channel h =======
    // wEff[c,h,k] = sum_ks scores[ks,k] * wb[c, ks*32+h]   (wb hoisted to regs)
    float wbr[3][8];
    #pragma unroll
    for (int c = 0; c < 3; c++)
        #pragma unroll
        for (int ks = 0; ks < 8; ks++)
            wbr[c][ks] = s_wb[c*256 + ks*32 + lane];

    float f0 = 0.0f, f1 = 0.0f, f2 = 0.0f;
    #pragma unroll
    for (int kk = 0; kk < 16; kk++) {
        float we0 = 0.0f, we1 = 0.0f, we2 = 0.0f;
        #pragma unroll
        for (int ks = 0; ks < 8; ks++) {
            const float sc = s_scores[warp][ks][kk];
            we0 += sc * wbr[0][ks];
            we1 += sc * wbr[1][ks];
            we2 += sc * wbr[2][ks];
        }
        const float l00 = s_local[warp][0][kk], l01 = s_local[warp][1][kk], l02 = s_local[warp][2][kk];
        const float l10 = s_local[warp][3][kk], l11 = s_local[warp][4][kk], l12 = s_local[warp][5][kk];
        const float l20 = s_local[warp][6][kk], l21 = s_local[warp][7][kk], l22 = s_local[warp][8][kk];
        const float p0 = l00*we0 + l10*we1 + l20*we2;
        const float p1 = l01*we0 + l11*we1 + l21*we2;
        const float p2 = l02*we0 + l12*we1 + l22*we2;
        const float nn = p0*p0 + p1*p1 + p2*p2;
        const float iv = rsqrtf(fmaxf(nn, 1e-24f));  // == 1/max(sqrt(nn),1e-12)
        f0 += p0*iv; f1 += p1*iv; f2 += p2*iv;
    }
    f0 *= (1.0f/16.0f); f1 *= (1.0f/16.0f); f2 *= (1.0f/16.0f);
    s_feats[warp][lane][0] = f0; s_feats[warp][lane][1] = f1; s_feats[warp][lane][2] = f2;
    __syncwarp();

    // ======= Phase 3a: VNLeakyReLU(32->32), lane = channel o =======
    float g0 = 0.0f, g1 = 0.0f, g2 = 0.0f;
    #pragma unroll
    for (int h = 0; h < 32; h++) {
        const float w = s_wdrelu[h*32 + lane];
        g0 += s_feats[warp][h][0] * w;
        g1 += s_feats[warp][h][1] * w;
        g2 += s_feats[warp][h][2] * w;
    }
    {
        const float dot = f0*g0 + f1*g1 + f2*g2;
        const float dsq = g0*g0 + g1*g1 + g2*g2;
        const float fc = (dot >= 0.0f) ? 0.0f : (0.8f * __fdividef(dot, dsq + 1e-6f));
        f0 -= fc*g0; f1 -= fc*g1; f2 -= fc*g2;
    }
    __syncwarp();
    s_feats[warp][lane][0] = f0; s_feats[warp][lane][1] = f1; s_feats[warp][lane][2] = f2;
    __syncwarp();

    // ======= Phase 3b: VNLinearLeakyReLU(32->64), lane handles j=lane, lane+32 =======
    #pragma unroll
    for (int rep = 0; rep < 2; rep++) {
        const int j = lane + rep*32;
        float a0=0,a1=0,a2=0,b0=0,b1=0,b2=0;
        #pragma unroll
        for (int h = 0; h < 32; h++) {
            const float fh0 = s_feats[warp][h][0];
            const float fh1 = s_feats[warp][h][1];
            const float fh2 = s_feats[warp][h][2];
            const float wa = s_wun [h*64 + j];
            const float wd = s_wdun[h*64 + j];
            a0 += fh0*wa; a1 += fh1*wa; a2 += fh2*wa;
            b0 += fh0*wd; b1 += fh1*wd; b2 += fh2*wd;
        }
        a0 *= BN; a1 *= BN; a2 *= BN;
        const float dt = a0*b0 + a1*b1 + a2*b2;
        const float dq = b0*b0 + b1*b1 + b2*b2;
        const float fc = (dt >= 0.0f) ? 0.0f : (0.8f * __fdividef(dt, dq + 1e-6f));
        out[n*192 + j*3 + 0] = a0 - fc*b0;
        out[n*192 + j*3 + 1] = a1 - fc*b1;
        out[n*192 + j*3 + 2] = a2 - fc*b2;
    }
}

extern "C" void kernel_launch(void* const* d_in, const int* in_sizes, int n_in,
                              void* d_out, int out_size) {
    const float* q_pts   = (const float*)d_in[0];
    const float* s_pts   = (const float*)d_in[1];
    // d_in[2] = s_feats : unused by the reference computation
    const int*   nbr     = (const int*)  d_in[3];
    const float* wb      = (const float*)d_in[4];
    const float* w_vn    = (const float*)d_in[5];
    const float* wd_vn   = (const float*)d_in[6];
    const float* w_h1    = (const float*)d_in[7];
    const float* w_h2    = (const float*)d_in[8];
    const float* b_h2    = (const float*)d_in[9];
    const float* wd_relu = (const float*)d_in[10];
    const float* w_un    = (const float*)d_in[11];
    const float* wd_un   = (const float*)d_in[12];

    const int N = in_sizes[0] / 3;
    const int blocks = (N + WARPS - 1) / WARPS;
    arek<<<blocks, 128>>>(q_pts, s_pts, nbr, wb, w_vn, wd_vn, w_h1, w_h2, b_h2,
                          wd_relu, w_un, wd_un, (float*)d_out, N);
}

// round 2
// speedup vs baseline: 1.0351x; 1.0351x over previous
#include <cuda_runtime.h>

#define WARPS 4
#define FULLMASK 0xffffffffu

__global__ void __launch_bounds__(128) arek(
    const float* __restrict__ q_pts, const float* __restrict__ s_pts,
    const int*   __restrict__ nbr,
    const float* __restrict__ wb,     const float* __restrict__ w_vn,
    const float* __restrict__ wd_vn,  const float* __restrict__ w_h1,
    const float* __restrict__ w_h2,   const float* __restrict__ b_h2,
    const float* __restrict__ wd_relu,const float* __restrict__ w_un,
    const float* __restrict__ wd_un,
    float* __restrict__ out, int N)
{
    // ---- weights, vector-friendly layouts ----
    __shared__ float4 s_wvnu[16][2];                 // [o] -> {w0,w1,w2,_},{u0,u1,u2,_}
    __shared__ __align__(16) float s_wh1[128];       // [16][8] row-major
    __shared__ __align__(16) float s_wh2[64];        // [8][8]  row-major
    __shared__ __align__(16) float s_bh2[8];
    __shared__ float s_wb[768];
    __shared__ float s_wdrelu[1024];
    __shared__ __align__(16) float s_wu2[4096];      // interleaved {w_un, wd_un} pairs
    // ---- per-warp scratch ----
    __shared__ float4 s_localv[WARPS][16][3];        // [k] -> {p},{c},{r} (w unused)
    __shared__ float4 s_scorev[WARPS][16][2];        // [k] -> scores[0..7]
    __shared__ float4 s_featv [WARPS][32];           // [h] -> {f0,f1,f2,_}

    const int tid = threadIdx.x;
    // ---- cooperative weight staging ----
    if (tid < 16) {
        const int o = tid;
        s_wvnu[o][0] = make_float4(w_vn [o], w_vn [16+o], w_vn [32+o], 0.0f);
        s_wvnu[o][1] = make_float4(wd_vn[o], wd_vn[16+o], wd_vn[32+o], 0.0f);
    }
    s_wh1[tid] = w_h1[tid];
    if (tid < 64) s_wh2[tid] = w_h2[tid];
    if (tid < 8)  s_bh2[tid] = b_h2[tid];
    #pragma unroll
    for (int i = tid; i < 768; i += 128) s_wb[i] = wb[i];
    #pragma unroll
    for (int i = tid; i < 1024; i += 128) s_wdrelu[i] = wd_relu[i];
    #pragma unroll
    for (int i = tid; i < 2048; i += 128) { s_wu2[2*i] = w_un[i]; s_wu2[2*i+1] = wd_un[i]; }
    __syncthreads();

    const int warp = tid >> 5, lane = tid & 31;
    const int n = blockIdx.x * WARPS + warp;
    if (n >= N) return;

    const float BN = 0.99999500003749968f;   // 1/sqrt(1+1e-5)

    // ================= Phase 1: per-neighbor score net =================
    const int k  = lane & 15;
    const int kh = lane >> 4;

    const float qx = q_pts[n*3+0], qy = q_pts[n*3+1], qz = q_pts[n*3+2];
    const int idx = nbr[n*16 + k];
    const float px = s_pts[idx*3+0] - qx;
    const float py = s_pts[idx*3+1] - qy;
    const float pz = s_pts[idx*3+2] - qz;

    float cx = px, cy = py, cz = pz;
    #pragma unroll
    for (int off = 16; off; off >>= 1) {
        cx += __shfl_xor_sync(FULLMASK, cx, off);
        cy += __shfl_xor_sync(FULLMASK, cy, off);
        cz += __shfl_xor_sync(FULLMASK, cz, off);
    }
    cx *= (1.0f/32.0f); cy *= (1.0f/32.0f); cz *= (1.0f/32.0f);

    const float rx = py*cz - pz*cy;
    const float ry = pz*cx - px*cz;
    const float rz = px*cy - py*cx;

    if (kh == 0) {
        s_localv[warp][k][0] = make_float4(px, py, pz, 0.0f);
        s_localv[warp][k][1] = make_float4(cx, cy, cz, 0.0f);
        s_localv[warp][k][2] = make_float4(rx, ry, rz, 0.0f);
    }

    // VN linear (3->16) + VN leaky relu + norm: each lane does 8 of 16 o's
    float sn[8];
    const int obase = kh * 8;
    #pragma unroll
    for (int oo = 0; oo < 8; oo++) {
        const float4 W = s_wvnu[obase + oo][0];
        const float4 U = s_wvnu[obase + oo][1];
        const float p0 = BN*(px*W.x + cx*W.y + rx*W.z);
        const float p1 = BN*(py*W.x + cy*W.y + ry*W.z);
        const float p2 = BN*(pz*W.x + cz*W.y + rz*W.z);
        const float d0 = px*U.x + cx*U.y + rx*U.z;
        const float d1 = py*U.x + cy*U.y + ry*U.z;
        const float d2 = pz*U.x + cz*U.y + rz*U.z;
        const float dot = p0*d0 + p1*d1 + p2*d2;
        const float dsq = d0*d0 + d1*d1 + d2*d2;
        const float f = (dot >= 0.0f) ? 0.0f : (0.8f * __fdividef(dot, dsq + 1e-6f));
        const float s0 = p0 - f*d0, s1 = p1 - f*d1, s2 = p2 - f*d2;
        sn[oo] = sqrtf(s0*s0 + s1*s1 + s2*s2);
    }

    // h1 = relu(BN * sn @ w_h1): row-major accumulation, float4 weight rows
    const float4* wh1v = (const float4*)s_wh1;
    float acc[8] = {0,0,0,0,0,0,0,0};
    #pragma unroll
    for (int c = 0; c < 8; c++) {
        const float4 r0 = wh1v[(obase + c)*2 + 0];
        const float4 r1 = wh1v[(obase + c)*2 + 1];
        const float s = sn[c];
        acc[0] += s*r0.x; acc[1] += s*r0.y; acc[2] += s*r0.z; acc[3] += s*r0.w;
        acc[4] += s*r1.x; acc[5] += s*r1.y; acc[6] += s*r1.z; acc[7] += s*r1.w;
    }
    float h1[8];
    #pragma unroll
    for (int o = 0; o < 8; o++) {
        float a = acc[o] + __shfl_xor_sync(FULLMASK, acc[o], 16);
        h1[o] = fmaxf(0.0f, BN * a);
    }

    // h2 + softmax over the 8 channels (row-major, float4 rows)
    const float4* wh2v = (const float4*)s_wh2;
    const float4 bA = ((const float4*)s_bh2)[0];
    const float4 bB = ((const float4*)s_bh2)[1];
    float h2[8] = {bA.x, bA.y, bA.z, bA.w, bB.x, bB.y, bB.z, bB.w};
    #pragma unroll
    for (int c = 0; c < 8; c++) {
        const float4 r0 = wh2v[c*2 + 0];
        const float4 r1 = wh2v[c*2 + 1];
        const float s = h1[c];
        h2[0] += s*r0.x; h2[1] += s*r0.y; h2[2] += s*r0.z; h2[3] += s*r0.w;
        h2[4] += s*r1.x; h2[5] += s*r1.y; h2[6] += s*r1.z; h2[7] += s*r1.w;
    }
    float m = h2[0];
    #pragma unroll
    for (int o = 1; o < 8; o++) m = fmaxf(m, h2[o]);
    float se = 0.0f;
    #pragma unroll
    for (int o = 0; o < 8; o++) { h2[o] = __expf(h2[o] - m); se += h2[o]; }
    const float ise = __fdividef(1.0f, se);
    if (kh == 0) {
        s_scorev[warp][k][0] = make_float4(h2[0]*ise, h2[1]*ise, h2[2]*ise, h2[3]*ise);
        s_scorev[warp][k][1] = make_float4(h2[4]*ise, h2[5]*ise, h2[6]*ise, h2[7]*ise);
    }
    __syncwarp();

    // ======= Phase 2: kernel-point correlation, lane = output channel h =======
    float wbr[3][8];
    #pragma unroll
    for (int c = 0; c < 3; c++)
        #pragma unroll
        for (int ks = 0; ks < 8; ks++)
            wbr[c][ks] = s_wb[c*256 + ks*32 + lane];

    float f0 = 0.0f, f1 = 0.0f, f2 = 0.0f;
    #pragma unroll
    for (int kk = 0; kk < 16; kk++) {
        const float4 sA = s_scorev[warp][kk][0];
        const float4 sB = s_scorev[warp][kk][1];
        float we0, we1, we2;
        we0 = sA.x*wbr[0][0] + sA.y*wbr[0][1] + sA.z*wbr[0][2] + sA.w*wbr[0][3]
            + sB.x*wbr[0][4] + sB.y*wbr[0][5] + sB.z*wbr[0][6] + sB.w*wbr[0][7];
        we1 = sA.x*wbr[1][0] + sA.y*wbr[1][1] + sA.z*wbr[1][2] + sA.w*wbr[1][3]
            + sB.x*wbr[1][4] + sB.y*wbr[1][5] + sB.z*wbr[1][6] + sB.w*wbr[1][7];
        we2 = sA.x*wbr[2][0] + sA.y*wbr[2][1] + sA.z*wbr[2][2] + sA.w*wbr[2][3]
            + sB.x*wbr[2][4] + sB.y*wbr[2][5] + sB.z*wbr[2][6] + sB.w*wbr[2][7];
        const float4 P = s_localv[warp][kk][0];
        const float4 C = s_localv[warp][kk][1];
        const float4 R = s_localv[warp][kk][2];
        const float p0 = P.x*we0 + C.x*we1 + R.x*we2;
        const float p1 = P.y*we0 + C.y*we1 + R.y*we2;
        const float p2 = P.z*we0 + C.z*we1 + R.z*we2;
        const float nn = p0*p0 + p1*p1 + p2*p2;
        const float iv = rsqrtf(fmaxf(nn, 1e-24f));
        f0 += p0*iv; f1 += p1*iv; f2 += p2*iv;
    }
    f0 *= (1.0f/16.0f); f1 *= (1.0f/16.0f); f2 *= (1.0f/16.0f);
    s_featv[warp][lane] = make_float4(f0, f1, f2, 0.0f);
    __syncwarp();

    // ======= Phase 3a: VNLeakyReLU(32->32), lane = channel o =======
    float g0 = 0.0f, g1 = 0.0f, g2 = 0.0f;
    #pragma unroll
    for (int h = 0; h < 32; h++) {
        const float4 F = s_featv[warp][h];
        const float w = s_wdrelu[h*32 + lane];
        g0 += F.x * w; g1 += F.y * w; g2 += F.z * w;
    }
    {
        const float dot = f0*g0 + f1*g1 + f2*g2;
        const float dsq = g0*g0 + g1*g1 + g2*g2;
        const float fc = (dot >= 0.0f) ? 0.0f : (0.8f * __fdividef(dot, dsq + 1e-6f));
        f0 -= fc*g0; f1 -= fc*g1; f2 -= fc*g2;
    }
    __syncwarp();
    s_featv[warp][lane] = make_float4(f0, f1, f2, 0.0f);
    __syncwarp();

    // ======= Phase 3b: VNLinearLeakyReLU(32->64), both halves fused =======
    const float2* wuv = (const float2*)s_wu2;   // [h*64 + j] -> {w_un, wd_un}
    float a0=0,a1=0,a2=0,b0=0,b1=0,b2=0;        // j = lane
    float A0=0,A1=0,A2=0,B0=0,B1=0,B2=0;        // j = lane + 32
    #pragma unroll
    for (int h = 0; h < 32; h++) {
        const float4 F  = s_featv[warp][h];
        const float2 w0 = wuv[h*64 + lane];
        const float2 w1 = wuv[h*64 + lane + 32];
        a0 += F.x*w0.x; a1 += F.y*w0.x; a2 += F.z*w0.x;
        b0 += F.x*w0.y; b1 += F.y*w0.y; b2 += F.z*w0.y;
        A0 += F.x*w1.x; A1 += F.y*w1.x; A2 += F.z*w1.x;
        B0 += F.x*w1.y; B1 += F.y*w1.y; B2 += F.z*w1.y;
    }
    {
        const int j = lane;
        const float x0 = BN*a0, x1 = BN*a1, x2 = BN*a2;
        const float dt = x0*b0 + x1*b1 + x2*b2;
        const float dq = b0*b0 + b1*b1 + b2*b2;
        const float fc = (dt >= 0.0f) ? 0.0f : (0.8f * __fdividef(dt, dq + 1e-6f));
        out[n*192 + j*3 + 0] = x0 - fc*b0;
        out[n*192 + j*3 + 1] = x1 - fc*b1;
        out[n*192 + j*3 + 2] = x2 - fc*b2;
    }
    {
        const int j = lane + 32;
        const float x0 = BN*A0, x1 = BN*A1, x2 = BN*A2;
        const float dt = x0*B0 + x1*B1 + x2*B2;
        const float dq = B0*B0 + B1*B1 + B2*B2;
        const float fc = (dt >= 0.0f) ? 0.0f : (0.8f * __fdividef(dt, dq + 1e-6f));
        out[n*192 + j*3 + 0] = x0 - fc*B0;
        out[n*192 + j*3 + 1] = x1 - fc*B1;
        out[n*192 + j*3 + 2] = x2 - fc*B2;
    }
}

extern "C" void kernel_launch(void* const* d_in, const int* in_sizes, int n_in,
                              void* d_out, int out_size) {
    const float* q_pts   = (const float*)d_in[0];
    const float* s_pts   = (const float*)d_in[1];
    const int*   nbr     = (const int*)  d_in[3];
    const float* wb      = (const float*)d_in[4];
    const float* w_vn    = (const float*)d_in[5];
    const float* wd_vn   = (const float*)d_in[6];
    const float* w_h1    = (const float*)d_in[7];
    const float* w_h2    = (const float*)d_in[8];
    const float* b_h2    = (const float*)d_in[9];
    const float* wd_relu = (const float*)d_in[10];
    const float* w_un    = (const float*)d_in[11];
    const float* wd_un   = (const float*)d_in[12];

    const int N = in_sizes[0] / 3;
    const int blocks = (N + WARPS - 1) / WARPS;
    arek<<<blocks, 128>>>(q_pts, s_pts, nbr, wb, w_vn, wd_vn, w_h1, w_h2, b_h2,
                          wd_relu, w_un, wd_un, (float*)d_out, N);
}

// round 3
// speedup vs baseline: 1.0832x; 1.0464x over previous
#include <cuda_runtime.h>

#define WARPS 4
#define PTS 2
#define FULLMASK 0xffffffffu

__device__ __forceinline__ unsigned long long pk2(float x, float y) {
    unsigned long long r;
    asm("mov.b64 %0,{%1,%2};" : "=l"(r) : "f"(x), "f"(y));
    return r;
}
__device__ __forceinline__ void upk2(unsigned long long v, float& x, float& y) {
    asm("mov.b64 {%0,%1},%2;" : "=f"(x), "=f"(y) : "l"(v));
}
__device__ __forceinline__ void ffma2(unsigned long long& d, unsigned long long a,
                                      unsigned long long b) {
    asm("fma.rn.f32x2 %0,%1,%2,%0;" : "+l"(d) : "l"(a), "l"(b));
}

__global__ void __launch_bounds__(128) arek(
    const float* __restrict__ q_pts, const float* __restrict__ s_pts,
    const int*   __restrict__ nbr,
    const float* __restrict__ wb,     const float* __restrict__ w_vn,
    const float* __restrict__ wd_vn,  const float* __restrict__ w_h1,
    const float* __restrict__ w_h2,   const float* __restrict__ b_h2,
    const float* __restrict__ wd_relu,const float* __restrict__ w_un,
    const float* __restrict__ wd_un,
    float* __restrict__ out, int N)
{
    // ---- weights ----
    __shared__ float4 s_wvnu[16][2];                 // [o] -> {w0,w1,w2,_},{u0,u1,u2,_}
    __shared__ __align__(16) float s_wh1[128];       // [16][8] row-major
    __shared__ __align__(16) float s_wh2[64];        // [8][8]  row-major
    __shared__ __align__(16) float s_bh2[8];
    __shared__ float s_wb[768];
    __shared__ float s_wdrelu[1024];
    __shared__ __align__(16) float s_wu2[4096];      // interleaved {w_un, wd_un} pairs
    // ---- per-warp scratch ----
    __shared__ float4 s_localv[WARPS][PTS][16][3];
    __shared__ float4 s_scorev[WARPS][PTS][16][2];
    __shared__ float4 s_featv [WARPS][PTS][32];

    const int tid = threadIdx.x;
    if (tid < 16) {
        const int o = tid;
        s_wvnu[o][0] = make_float4(w_vn [o], w_vn [16+o], w_vn [32+o], 0.0f);
        s_wvnu[o][1] = make_float4(wd_vn[o], wd_vn[16+o], wd_vn[32+o], 0.0f);
    }
    s_wh1[tid] = w_h1[tid];
    if (tid < 64) s_wh2[tid] = w_h2[tid];
    if (tid < 8)  s_bh2[tid] = b_h2[tid];
    #pragma unroll
    for (int i = tid; i < 768; i += 128) s_wb[i] = wb[i];
    #pragma unroll
    for (int i = tid; i < 1024; i += 128) s_wdrelu[i] = wd_relu[i];
    #pragma unroll
    for (int i = tid; i < 2048; i += 128) { s_wu2[2*i] = w_un[i]; s_wu2[2*i+1] = wd_un[i]; }
    __syncthreads();

    const int warp = tid >> 5, lane = tid & 31;
    const int n0 = blockIdx.x * (WARPS * PTS) + warp * PTS;
    if (n0 >= N) return;

    const float BN = 0.99999500003749968f;   // 1/sqrt(1+1e-5)
    const int k  = lane & 15;
    const int kh = lane >> 4;
    const int obase = kh * 8;

    // ================= Phase 1: geometry for both points =================
    float px[PTS], py[PTS], pz[PTS], cx[PTS], cy[PTS], cz[PTS], rx[PTS], ry[PTS], rz[PTS];
    #pragma unroll
    for (int p = 0; p < PTS; p++) {
        const int n = (n0 + p < N) ? (n0 + p) : (N - 1);
        const float qx = q_pts[n*3+0], qy = q_pts[n*3+1], qz = q_pts[n*3+2];
        const int idx = nbr[n*16 + k];
        px[p] = s_pts[idx*3+0] - qx;
        py[p] = s_pts[idx*3+1] - qy;
        pz[p] = s_pts[idx*3+2] - qz;
        float sx = px[p], sy = py[p], sz = pz[p];
        #pragma unroll
        for (int off = 16; off; off >>= 1) {
            sx += __shfl_xor_sync(FULLMASK, sx, off);
            sy += __shfl_xor_sync(FULLMASK, sy, off);
            sz += __shfl_xor_sync(FULLMASK, sz, off);
        }
        cx[p] = sx * (1.0f/32.0f); cy[p] = sy * (1.0f/32.0f); cz[p] = sz * (1.0f/32.0f);
        rx[p] = py[p]*cz[p] - pz[p]*cy[p];
        ry[p] = pz[p]*cx[p] - px[p]*cz[p];
        rz[p] = px[p]*cy[p] - py[p]*cx[p];
        if (kh == 0) {
            s_localv[warp][p][k][0] = make_float4(px[p], py[p], pz[p], 0.0f);
            s_localv[warp][p][k][1] = make_float4(cx[p], cy[p], cz[p], 0.0f);
            s_localv[warp][p][k][2] = make_float4(rx[p], ry[p], rz[p], 0.0f);
        }
    }

    // VN linear (3->16) + VN leaky relu + norm; weights amortized over PTS
    float sn[PTS][8];
    #pragma unroll
    for (int oo = 0; oo < 8; oo++) {
        const float4 W = s_wvnu[obase + oo][0];
        const float4 U = s_wvnu[obase + oo][1];
        #pragma unroll
        for (int p = 0; p < PTS; p++) {
            const float p0 = BN*(px[p]*W.x + cx[p]*W.y + rx[p]*W.z);
            const float p1 = BN*(py[p]*W.x + cy[p]*W.y + ry[p]*W.z);
            const float p2 = BN*(pz[p]*W.x + cz[p]*W.y + rz[p]*W.z);
            const float d0 = px[p]*U.x + cx[p]*U.y + rx[p]*U.z;
            const float d1 = py[p]*U.x + cy[p]*U.y + ry[p]*U.z;
            const float d2 = pz[p]*U.x + cz[p]*U.y + rz[p]*U.z;
            const float dot = p0*d0 + p1*d1 + p2*d2;
            const float dsq = d0*d0 + d1*d1 + d2*d2;
            const float f = (dot >= 0.0f) ? 0.0f : (0.8f * __fdividef(dot, dsq + 1e-6f));
            const float s0 = p0 - f*d0, s1 = p1 - f*d1, s2 = p2 - f*d2;
            sn[p][oo] = sqrtf(s0*s0 + s1*s1 + s2*s2);
        }
    }

    // h1 = relu(BN * sn @ w_h1); weights amortized over PTS
    const float4* wh1v = (const float4*)s_wh1;
    float h1[PTS][8];
    {
        float acc[PTS][8];
        #pragma unroll
        for (int p = 0; p < PTS; p++)
            #pragma unroll
            for (int o = 0; o < 8; o++) acc[p][o] = 0.0f;
        #pragma unroll
        for (int c = 0; c < 8; c++) {
            const float4 r0 = wh1v[(obase + c)*2 + 0];
            const float4 r1 = wh1v[(obase + c)*2 + 1];
            #pragma unroll
            for (int p = 0; p < PTS; p++) {
                const float s = sn[p][c];
                acc[p][0] += s*r0.x; acc[p][1] += s*r0.y; acc[p][2] += s*r0.z; acc[p][3] += s*r0.w;
                acc[p][4] += s*r1.x; acc[p][5] += s*r1.y; acc[p][6] += s*r1.z; acc[p][7] += s*r1.w;
            }
        }
        #pragma unroll
        for (int p = 0; p < PTS; p++)
            #pragma unroll
            for (int o = 0; o < 8; o++) {
                const float a = acc[p][o] + __shfl_xor_sync(FULLMASK, acc[p][o], 16);
                h1[p][o] = fmaxf(0.0f, BN * a);
            }
    }

    // h2 + softmax; weights amortized over PTS
    {
        const float4* wh2v = (const float4*)s_wh2;
        const float4 bA = ((const float4*)s_bh2)[0];
        const float4 bB = ((const float4*)s_bh2)[1];
        float h2[PTS][8];
        #pragma unroll
        for (int p = 0; p < PTS; p++) {
            h2[p][0]=bA.x; h2[p][1]=bA.y; h2[p][2]=bA.z; h2[p][3]=bA.w;
            h2[p][4]=bB.x; h2[p][5]=bB.y; h2[p][6]=bB.z; h2[p][7]=bB.w;
        }
        #pragma unroll
        for (int c = 0; c < 8; c++) {
            const float4 r0 = wh2v[c*2 + 0];
            const float4 r1 = wh2v[c*2 + 1];
            #pragma unroll
            for (int p = 0; p < PTS; p++) {
                const float s = h1[p][c];
                h2[p][0] += s*r0.x; h2[p][1] += s*r0.y; h2[p][2] += s*r0.z; h2[p][3] += s*r0.w;
                h2[p][4] += s*r1.x; h2[p][5] += s*r1.y; h2[p][6] += s*r1.z; h2[p][7] += s*r1.w;
            }
        }
        #pragma unroll
        for (int p = 0; p < PTS; p++) {
            float m = h2[p][0];
            #pragma unroll
            for (int o = 1; o < 8; o++) m = fmaxf(m, h2[p][o]);
            float se = 0.0f;
            #pragma unroll
            for (int o = 0; o < 8; o++) { h2[p][o] = __expf(h2[p][o] - m); se += h2[p][o]; }
            const float ise = __fdividef(1.0f, se);
            if (kh == 0) {
                s_scorev[warp][p][k][0] = make_float4(h2[p][0]*ise, h2[p][1]*ise, h2[p][2]*ise, h2[p][3]*ise);
                s_scorev[warp][p][k][1] = make_float4(h2[p][4]*ise, h2[p][5]*ise, h2[p][6]*ise, h2[p][7]*ise);
            }
        }
    }
    __syncwarp();

    // ======= Phase 2: kernel-point correlation, lane = output channel h =======
    float wb0[8], wb1[8], wb2[8];
    #pragma unroll
    for (int ks = 0; ks < 8; ks++) {
        wb0[ks] = s_wb[      ks*32 + lane];
        wb1[ks] = s_wb[256 + ks*32 + lane];
        wb2[ks] = s_wb[512 + ks*32 + lane];
    }
    #pragma unroll
    for (int p = 0; p < PTS; p++) {
        float f0 = 0.0f, f1 = 0.0f, f2 = 0.0f;
        #pragma unroll
        for (int kk = 0; kk < 16; kk++) {
            const float4 sA = s_scorev[warp][p][kk][0];
            const float4 sB = s_scorev[warp][p][kk][1];
            const float we0 = sA.x*wb0[0] + sA.y*wb0[1] + sA.z*wb0[2] + sA.w*wb0[3]
                            + sB.x*wb0[4] + sB.y*wb0[5] + sB.z*wb0[6] + sB.w*wb0[7];
            const float we1 = sA.x*wb1[0] + sA.y*wb1[1] + sA.z*wb1[2] + sA.w*wb1[3]
                            + sB.x*wb1[4] + sB.y*wb1[5] + sB.z*wb1[6] + sB.w*wb1[7];
            const float we2 = sA.x*wb2[0] + sA.y*wb2[1] + sA.z*wb2[2] + sA.w*wb2[3]
                            + sB.x*wb2[4] + sB.y*wb2[5] + sB.z*wb2[6] + sB.w*wb2[7];
            const float4 P = s_localv[warp][p][kk][0];
            const float4 C = s_localv[warp][p][kk][1];
            const float4 R = s_localv[warp][p][kk][2];
            const float p0 = P.x*we0 + C.x*we1 + R.x*we2;
            const float p1 = P.y*we0 + C.y*we1 + R.y*we2;
            const float p2 = P.z*we0 + C.z*we1 + R.z*we2;
            const float nn = p0*p0 + p1*p1 + p2*p2;
            const float iv = rsqrtf(fmaxf(nn, 1e-24f));
            f0 += p0*iv; f1 += p1*iv; f2 += p2*iv;
        }
        s_featv[warp][p][lane] = make_float4(f0*(1.0f/16.0f), f1*(1.0f/16.0f), f2*(1.0f/16.0f), 0.0f);
    }
    __syncwarp();

    // ======= Phase 3a: VNLeakyReLU(32->32), lane = channel, batched over PTS =======
    {
        float f[PTS][3], g[PTS][3];
        #pragma unroll
        for (int p = 0; p < PTS; p++) {
            const float4 F = s_featv[warp][p][lane];
            f[p][0] = F.x; f[p][1] = F.y; f[p][2] = F.z;
            g[p][0] = 0.0f; g[p][1] = 0.0f; g[p][2] = 0.0f;
        }
        #pragma unroll
        for (int h = 0; h < 32; h++) {
            const float w = s_wdrelu[h*32 + lane];
            #pragma unroll
            for (int p = 0; p < PTS; p++) {
                const float4 F = s_featv[warp][p][h];
                g[p][0] += F.x * w; g[p][1] += F.y * w; g[p][2] += F.z * w;
            }
        }
        __syncwarp();
        #pragma unroll
        for (int p = 0; p < PTS; p++) {
            const float dot = f[p][0]*g[p][0] + f[p][1]*g[p][1] + f[p][2]*g[p][2];
            const float dsq = g[p][0]*g[p][0] + g[p][1]*g[p][1] + g[p][2]*g[p][2];
            const float fc = (dot >= 0.0f) ? 0.0f : (0.8f * __fdividef(dot, dsq + 1e-6f));
            s_featv[warp][p][lane] = make_float4(f[p][0] - fc*g[p][0],
                                                 f[p][1] - fc*g[p][1],
                                                 f[p][2] - fc*g[p][2], 0.0f);
        }
    }
    __syncwarp();

    // ======= Phase 3b: VNLinearLeakyReLU(32->64), batched + f32x2-packed =======
    {
        const float2* wuv = (const float2*)s_wu2;   // [h*64 + j] -> {w_un, wd_un}
        unsigned long long a01[PTS], b01[PTS], A01[PTS], B01[PTS];
        float a2[PTS], b2[PTS], A2[PTS], B2[PTS];
        #pragma unroll
        for (int p = 0; p < PTS; p++) {
            a01[p] = 0ull; b01[p] = 0ull; A01[p] = 0ull; B01[p] = 0ull;
            a2[p] = 0.0f;  b2[p] = 0.0f;  A2[p] = 0.0f;  B2[p] = 0.0f;
        }
        #pragma unroll
        for (int h = 0; h < 32; h++) {
            const float2 w0 = wuv[h*64 + lane];
            const float2 w1 = wuv[h*64 + lane + 32];
            const unsigned long long w0x = pk2(w0.x, w0.x);
            const unsigned long long w0y = pk2(w0.y, w0.y);
            const unsigned long long w1x = pk2(w1.x, w1.x);
            const unsigned long long w1y = pk2(w1.y, w1.y);
            #pragma unroll
            for (int p = 0; p < PTS; p++) {
                const float4 F = s_featv[warp][p][h];
                const unsigned long long fxy = pk2(F.x, F.y);
                ffma2(a01[p], fxy, w0x); a2[p] += F.z * w0.x;
                ffma2(b01[p], fxy, w0y); b2[p] += F.z * w0.y;
                ffma2(A01[p], fxy, w1x); A2[p] += F.z * w1.x;
                ffma2(B01[p], fxy, w1y); B2[p] += F.z * w1.y;
            }
        }
        #pragma unroll
        for (int p = 0; p < PTS; p++) {
            if (n0 + p >= N) break;
            const int n = n0 + p;
            float a0, a1, b0, b1, A0, A1, B0, B1;
            upk2(a01[p], a0, a1); upk2(b01[p], b0, b1);
            upk2(A01[p], A0, A1); upk2(B01[p], B0, B1);
            {
                const int j = lane;
                const float x0 = BN*a0, x1 = BN*a1, x2 = BN*a2[p];
                const float dt = x0*b0 + x1*b1 + x2*b2[p];
                const float dq = b0*b0 + b1*b1 + b2[p]*b2[p];
                const float fc = (dt >= 0.0f) ? 0.0f : (0.8f * __fdividef(dt, dq + 1e-6f));
                out[n*192 + j*3 + 0] = x0 - fc*b0;
                out[n*192 + j*3 + 1] = x1 - fc*b1;
                out[n*192 + j*3 + 2] = x2 - fc*b2[p];
            }
            {
                const int j = lane + 32;
                const float x0 = BN*A0, x1 = BN*A1, x2 = BN*A2[p];
                const float dt = x0*B0 + x1*B1 + x2*B2[p];
                const float dq = B0*B0 + B1*B1 + B2[p]*B2[p];
                const float fc = (dt >= 0.0f) ? 0.0f : (0.8f * __fdividef(dt, dq + 1e-6f));
                out[n*192 + j*3 + 0] = x0 - fc*B0;
                out[n*192 + j*3 + 1] = x1 - fc*B1;
                out[n*192 + j*3 + 2] = x2 - fc*B2[p];
            }
        }
    }
}

extern "C" void kernel_launch(void* const* d_in, const int* in_sizes, int n_in,
                              void* d_out, int out_size) {
    const float* q_pts   = (const float*)d_in[0];
    const float* s_pts   = (const float*)d_in[1];
    const int*   nbr     = (const int*)  d_in[3];
    const float* wb      = (const float*)d_in[4];
    const float* w_vn    = (const float*)d_in[5];
    const float* wd_vn   = (const float*)d_in[6];
    const float* w_h1    = (const float*)d_in[7];
    const float* w_h2    = (const float*)d_in[8];
    const float* b_h2    = (const float*)d_in[9];
    const float* wd_relu = (const float*)d_in[10];
    const float* w_un    = (const float*)d_in[11];
    const float* wd_un   = (const float*)d_in[12];

    const int N = in_sizes[0] / 3;
    const int per_block = WARPS * PTS;
    const int blocks = (N + per_block - 1) / per_block;
    arek<<<blocks, 128>>>(q_pts, s_pts, nbr, wb, w_vn, wd_vn, w_h1, w_h2, b_h2,
                          wd_relu, w_un, wd_un, (float*)d_out, N);
}

// round 4
// speedup vs baseline: 1.1298x; 1.0430x over previous
#include <cuda_runtime.h>

#define WARPS 4
#define PTS 2
#define FULLMASK 0xffffffffu

__device__ __forceinline__ unsigned long long pk2(float x, float y) {
    unsigned long long r;
    asm("mov.b64 %0,{%1,%2};" : "=l"(r) : "f"(x), "f"(y));
    return r;
}
__device__ __forceinline__ void upk2(unsigned long long v, float& x, float& y) {
    asm("mov.b64 {%0,%1},%2;" : "=f"(x), "=f"(y) : "l"(v));
}
__device__ __forceinline__ void ffma2(unsigned long long& d, unsigned long long a,
                                      unsigned long long b) {
    asm("fma.rn.f32x2 %0,%1,%2,%0;" : "+l"(d) : "l"(a), "l"(b));
}

__global__ void __launch_bounds__(128, 6) arek(
    const float* __restrict__ q_pts, const float* __restrict__ s_pts,
    const int*   __restrict__ nbr,
    const float* __restrict__ wb,     const float* __restrict__ w_vn,
    const float* __restrict__ wd_vn,  const float* __restrict__ w_h1,
    const float* __restrict__ w_h2,   const float* __restrict__ b_h2,
    const float* __restrict__ wd_relu,const float* __restrict__ w_un,
    const float* __restrict__ wd_un,
    float* __restrict__ out, int N)
{
    // ---- weights ----
    __shared__ float4 s_wvnu[16][2];                 // [o] -> {w0,w1,w2,_},{u0,u1,u2,_}
    __shared__ __align__(16) float s_wh1[128];       // [16][8] row-major
    __shared__ __align__(16) float s_wh2[64];        // [8][8]  row-major
    __shared__ __align__(16) float s_bh2[8];
    __shared__ float s_wb[768];
    __shared__ float s_wdrelu[1024];
    __shared__ __align__(16) float s_wu2[4096];      // interleaved {w_un, wd_un} pairs
    // ---- per-warp scratch ----
    __shared__ float4 s_localv[WARPS][PTS][16][3];
    __shared__ float4 s_scorev[WARPS][PTS][16][2];
    __shared__ float4 s_featv [WARPS][PTS][32];

    const int tid = threadIdx.x;
    if (tid < 16) {
        const int o = tid;
        s_wvnu[o][0] = make_float4(w_vn [o], w_vn [16+o], w_vn [32+o], 0.0f);
        s_wvnu[o][1] = make_float4(wd_vn[o], wd_vn[16+o], wd_vn[32+o], 0.0f);
    }
    s_wh1[tid] = w_h1[tid];
    if (tid < 64) s_wh2[tid] = w_h2[tid];
    if (tid < 8)  s_bh2[tid] = b_h2[tid];
    #pragma unroll
    for (int i = tid; i < 768; i += 128) s_wb[i] = wb[i];
    #pragma unroll
    for (int i = tid; i < 1024; i += 128) s_wdrelu[i] = wd_relu[i];
    #pragma unroll
    for (int i = tid; i < 2048; i += 128) { s_wu2[2*i] = w_un[i]; s_wu2[2*i+1] = wd_un[i]; }
    __syncthreads();

    const int warp = tid >> 5, lane = tid & 31;
    const int n0 = blockIdx.x * (WARPS * PTS) + warp * PTS;
    if (n0 >= N) return;

    const float BN = 0.99999500003749968f;   // 1/sqrt(1+1e-5)

    // ================= Phase 1: lane = (p, k) — one neighbor per lane =================
    {
        const int pp = lane >> 4;            // point within pair
        const int k  = lane & 15;            // neighbor
        const int n  = (n0 + pp < N) ? (n0 + pp) : (N - 1);

        const float qx = q_pts[n*3+0], qy = q_pts[n*3+1], qz = q_pts[n*3+2];
        const int idx = nbr[n*16 + k];
        const float px = s_pts[idx*3+0] - qx;
        const float py = s_pts[idx*3+1] - qy;
        const float pz = s_pts[idx*3+2] - qz;

        // mean over the 16 neighbors of this point (segment reduce within half-warp)
        float sx = px, sy = py, sz = pz;
        #pragma unroll
        for (int off = 1; off < 16; off <<= 1) {
            sx += __shfl_xor_sync(FULLMASK, sx, off);
            sy += __shfl_xor_sync(FULLMASK, sy, off);
            sz += __shfl_xor_sync(FULLMASK, sz, off);
        }
        const float cx = sx * (1.0f/16.0f);
        const float cy = sy * (1.0f/16.0f);
        const float cz = sz * (1.0f/16.0f);

        const float rx = py*cz - pz*cy;
        const float ry = pz*cx - px*cz;
        const float rz = px*cy - py*cx;

        s_localv[warp][pp][k][0] = make_float4(px, py, pz, 0.0f);
        s_localv[warp][pp][k][1] = make_float4(cx, cy, cz, 0.0f);
        s_localv[warp][pp][k][2] = make_float4(rx, ry, rz, 0.0f);

        // VN 3->16 + VN-leakyReLU + norm, fused into the h1 matvec (sn consumed on the fly)
        const float4* wh1v = (const float4*)s_wh1;
        float acc[8] = {0,0,0,0,0,0,0,0};
        #pragma unroll
        for (int c = 0; c < 16; c++) {
            const float4 W = s_wvnu[c][0];
            const float4 U = s_wvnu[c][1];
            const float p0 = BN*(px*W.x + cx*W.y + rx*W.z);
            const float p1 = BN*(py*W.x + cy*W.y + ry*W.z);
            const float p2 = BN*(pz*W.x + cz*W.y + rz*W.z);
            const float d0 = px*U.x + cx*U.y + rx*U.z;
            const float d1 = py*U.x + cy*U.y + ry*U.z;
            const float d2 = pz*U.x + cz*U.y + rz*U.z;
            const float dot = p0*d0 + p1*d1 + p2*d2;
            const float dsq = d0*d0 + d1*d1 + d2*d2;
            const float f = (dot >= 0.0f) ? 0.0f : (0.8f * __fdividef(dot, dsq + 1e-6f));
            const float s0 = p0 - f*d0, s1 = p1 - f*d1, s2 = p2 - f*d2;
            const float sn = sqrtf(s0*s0 + s1*s1 + s2*s2);
            const float4 r0 = wh1v[c*2 + 0];
            const float4 r1 = wh1v[c*2 + 1];
            acc[0] += sn*r0.x; acc[1] += sn*r0.y; acc[2] += sn*r0.z; acc[3] += sn*r0.w;
            acc[4] += sn*r1.x; acc[5] += sn*r1.y; acc[6] += sn*r1.z; acc[7] += sn*r1.w;
        }
        #pragma unroll
        for (int o = 0; o < 8; o++) acc[o] = fmaxf(0.0f, BN * acc[o]);

        // h2 + softmax over 8 channels
        const float4* wh2v = (const float4*)s_wh2;
        const float4 bA = ((const float4*)s_bh2)[0];
        const float4 bB = ((const float4*)s_bh2)[1];
        float h2[8] = {bA.x, bA.y, bA.z, bA.w, bB.x, bB.y, bB.z, bB.w};
        #pragma unroll
        for (int c = 0; c < 8; c++) {
            const float4 r0 = wh2v[c*2 + 0];
            const float4 r1 = wh2v[c*2 + 1];
            const float s = acc[c];
            h2[0] += s*r0.x; h2[1] += s*r0.y; h2[2] += s*r0.z; h2[3] += s*r0.w;
            h2[4] += s*r1.x; h2[5] += s*r1.y; h2[6] += s*r1.z; h2[7] += s*r1.w;
        }
        float m = h2[0];
        #pragma unroll
        for (int o = 1; o < 8; o++) m = fmaxf(m, h2[o]);
        float se = 0.0f;
        #pragma unroll
        for (int o = 0; o < 8; o++) { h2[o] = __expf(h2[o] - m); se += h2[o]; }
        const float ise = __fdividef(1.0f, se);
        s_scorev[warp][pp][k][0] = make_float4(h2[0]*ise, h2[1]*ise, h2[2]*ise, h2[3]*ise);
        s_scorev[warp][pp][k][1] = make_float4(h2[4]*ise, h2[5]*ise, h2[6]*ise, h2[7]*ise);
    }
    __syncwarp();

    // ======= Phase 2: kernel-point correlation, lane = output channel h =======
    float wb0[8], wb1[8], wb2[8];
    #pragma unroll
    for (int ks = 0; ks < 8; ks++) {
        wb0[ks] = s_wb[      ks*32 + lane];
        wb1[ks] = s_wb[256 + ks*32 + lane];
        wb2[ks] = s_wb[512 + ks*32 + lane];
    }
    #pragma unroll
    for (int p = 0; p < PTS; p++) {
        float f0 = 0.0f, f1 = 0.0f, f2 = 0.0f;
        #pragma unroll
        for (int kk = 0; kk < 16; kk++) {
            const float4 sA = s_scorev[warp][p][kk][0];
            const float4 sB = s_scorev[warp][p][kk][1];
            const float we0 = sA.x*wb0[0] + sA.y*wb0[1] + sA.z*wb0[2] + sA.w*wb0[3]
                            + sB.x*wb0[4] + sB.y*wb0[5] + sB.z*wb0[6] + sB.w*wb0[7];
            const float we1 = sA.x*wb1[0] + sA.y*wb1[1] + sA.z*wb1[2] + sA.w*wb1[3]
                            + sB.x*wb1[4] + sB.y*wb1[5] + sB.z*wb1[6] + sB.w*wb1[7];
            const float we2 = sA.x*wb2[0] + sA.y*wb2[1] + sA.z*wb2[2] + sA.w*wb2[3]
                            + sB.x*wb2[4] + sB.y*wb2[5] + sB.z*wb2[6] + sB.w*wb2[7];
            const float4 P = s_localv[warp][p][kk][0];
            const float4 C = s_localv[warp][p][kk][1];
            const float4 R = s_localv[warp][p][kk][2];
            const float p0 = P.x*we0 + C.x*we1 + R.x*we2;
            const float p1 = P.y*we0 + C.y*we1 + R.y*we2;
            const float p2 = P.z*we0 + C.z*we1 + R.z*we2;
            const float nn = p0*p0 + p1*p1 + p2*p2;
            const float iv = rsqrtf(fmaxf(nn, 1e-24f));
            f0 += p0*iv; f1 += p1*iv; f2 += p2*iv;
        }
        s_featv[warp][p][lane] = make_float4(f0*(1.0f/16.0f), f1*(1.0f/16.0f), f2*(1.0f/16.0f), 0.0f);
    }
    __syncwarp();

    // ======= Phase 3a: VNLeakyReLU(32->32), lane = channel, batched over PTS =======
    {
        float f[PTS][3], g[PTS][3];
        #pragma unroll
        for (int p = 0; p < PTS; p++) {
            const float4 F = s_featv[warp][p][lane];
            f[p][0] = F.x; f[p][1] = F.y; f[p][2] = F.z;
            g[p][0] = 0.0f; g[p][1] = 0.0f; g[p][2] = 0.0f;
        }
        #pragma unroll
        for (int h = 0; h < 32; h++) {
            const float w = s_wdrelu[h*32 + lane];
            #pragma unroll
            for (int p = 0; p < PTS; p++) {
                const float4 F = s_featv[warp][p][h];
                g[p][0] += F.x * w; g[p][1] += F.y * w; g[p][2] += F.z * w;
            }
        }
        __syncwarp();
        #pragma unroll
        for (int p = 0; p < PTS; p++) {
            const float dot = f[p][0]*g[p][0] + f[p][1]*g[p][1] + f[p][2]*g[p][2];
            const float dsq = g[p][0]*g[p][0] + g[p][1]*g[p][1] + g[p][2]*g[p][2];
            const float fc = (dot >= 0.0f) ? 0.0f : (0.8f * __fdividef(dot, dsq + 1e-6f));
            s_featv[warp][p][lane] = make_float4(f[p][0] - fc*g[p][0],
                                                 f[p][1] - fc*g[p][1],
                                                 f[p][2] - fc*g[p][2], 0.0f);
        }
    }
    __syncwarp();

    // ======= Phase 3b: VNLinearLeakyReLU(32->64), batched + f32x2-packed =======
    {
        const float2* wuv = (const float2*)s_wu2;   // [h*64 + j] -> {w_un, wd_un}
        unsigned long long a01[PTS], b01[PTS], A01[PTS], B01[PTS];
        float a2[PTS], b2[PTS], A2[PTS], B2[PTS];
        #pragma unroll
        for (int p = 0; p < PTS; p++) {
            a01[p] = 0ull; b01[p] = 0ull; A01[p] = 0ull; B01[p] = 0ull;
            a2[p] = 0.0f;  b2[p] = 0.0f;  A2[p] = 0.0f;  B2[p] = 0.0f;
        }
        #pragma unroll
        for (int h = 0; h < 32; h++) {
            const float2 w0 = wuv[h*64 + lane];
            const float2 w1 = wuv[h*64 + lane + 32];
            const unsigned long long w0x = pk2(w0.x, w0.x);
            const unsigned long long w0y = pk2(w0.y, w0.y);
            const unsigned long long w1x = pk2(w1.x, w1.x);
            const unsigned long long w1y = pk2(w1.y, w1.y);
            #pragma unroll
            for (int p = 0; p < PTS; p++) {
                const float4 F = s_featv[warp][p][h];
                const unsigned long long fxy = pk2(F.x, F.y);
                ffma2(a01[p], fxy, w0x); a2[p] += F.z * w0.x;
                ffma2(b01[p], fxy, w0y); b2[p] += F.z * w0.y;
                ffma2(A01[p], fxy, w1x); A2[p] += F.z * w1.x;
                ffma2(B01[p], fxy, w1y); B2[p] += F.z * w1.y;
            }
        }
        #pragma unroll
        for (int p = 0; p < PTS; p++) {
            if (n0 + p >= N) break;
            const int n = n0 + p;
            float a0, a1, b0, b1, A0, A1, B0, B1;
            upk2(a01[p], a0, a1); upk2(b01[p], b0, b1);
            upk2(A01[p], A0, A1); upk2(B01[p], B0, B1);
            {
                const int j = lane;
                const float x0 = BN*a0, x1 = BN*a1, x2 = BN*a2[p];
                const float dt = x0*b0 + x1*b1 + x2*b2[p];
                const float dq = b0*b0 + b1*b1 + b2[p]*b2[p];
                const float fc = (dt >= 0.0f) ? 0.0f : (0.8f * __fdividef(dt, dq + 1e-6f));
                out[n*192 + j*3 + 0] = x0 - fc*b0;
                out[n*192 + j*3 + 1] = x1 - fc*b1;
                out[n*192 + j*3 + 2] = x2 - fc*b2[p];
            }
            {
                const int j = lane + 32;
                const float x0 = BN*A0, x1 = BN*A1, x2 = BN*A2[p];
                const float dt = x0*B0 + x1*B1 + x2*B2[p];
                const float dq = B0*B0 + B1*B1 + B2[p]*B2[p];
                const float fc = (dt >= 0.0f) ? 0.0f : (0.8f * __fdividef(dt, dq + 1e-6f));
                out[n*192 + j*3 + 0] = x0 - fc*B0;
                out[n*192 + j*3 + 1] = x1 - fc*B1;
                out[n*192 + j*3 + 2] = x2 - fc*B2[p];
            }
        }
    }
}

extern "C" void kernel_launch(void* const* d_in, const int* in_sizes, int n_in,
                              void* d_out, int out_size) {
    const float* q_pts   = (const float*)d_in[0];
    const float* s_pts   = (const float*)d_in[1];
    const int*   nbr     = (const int*)  d_in[3];
    const float* wb      = (const float*)d_in[4];
    const float* w_vn    = (const float*)d_in[5];
    const float* wd_vn   = (const float*)d_in[6];
    const float* w_h1    = (const float*)d_in[7];
    const float* w_h2    = (const float*)d_in[8];
    const float* b_h2    = (const float*)d_in[9];
    const float* wd_relu = (const float*)d_in[10];
    const float* w_un    = (const float*)d_in[11];
    const float* wd_un   = (const float*)d_in[12];

    const int N = in_sizes[0] / 3;
    const int per_block = WARPS * PTS;
    const int blocks = (N + per_block - 1) / per_block;
    arek<<<blocks, 128>>>(q_pts, s_pts, nbr, wb, w_vn, wd_vn, w_h1, w_h2, b_h2,
                          wd_relu, w_un, wd_un, (float*)d_out, N);
}